// round 4
// baseline (speedup 1.0000x reference)
#include <cuda_runtime.h>
#include <cuda_bf16.h>
#include <stdint.h>

#define BATCH      32
#define SEQ_T      512
#define DIM        512
#define MAX_FRAMES 4096
#define ROW_BYTES  (DIM * 4)                 // 2048 B per row
#define F4_ROW     (DIM / 4)                 // 128 float4 per row
#define FPB        16                        // frames per gather block
#define GB_THREADS 128
#define GB_GRID    (BATCH * MAX_FRAMES / FPB)   // 8192

// frame -> source-row map; -1 means masked. 256 KB static scratch.
__device__ int16_t g_frame2row[BATCH * MAX_FRAMES];

__device__ __forceinline__ uint32_t s2u(const void* p) {
    return (uint32_t)__cvta_generic_to_shared(p);
}

// ---------------------------------------------------------------------------
// Kernel A: per-batch inclusive scan (warp-shuffle) + scatter frame->row map.
// ---------------------------------------------------------------------------
__global__ void lr_scan_map_kernel(const int* __restrict__ durations,
                                   float* __restrict__ mel_lens_out)
{
    const int b    = blockIdx.x;
    const int t    = threadIdx.x;       // 0..511
    const int lane = t & 31;
    const int warp = t >> 5;            // 0..15

    __shared__ int s_warpsum[16];
    __shared__ int s_total;

    int d = durations[b * SEQ_T + t];

    int v = d;
    #pragma unroll
    for (int off = 1; off < 32; off <<= 1) {
        int n = __shfl_up_sync(0xffffffffu, v, off);
        if (lane >= off) v += n;
    }
    if (lane == 31) s_warpsum[warp] = v;
    __syncthreads();

    if (warp == 0) {
        int ws = (lane < 16) ? s_warpsum[lane] : 0;
        #pragma unroll
        for (int off = 1; off < 16; off <<= 1) {
            int n = __shfl_up_sync(0xffffffffu, ws, off);
            if (lane >= off) ws += n;
        }
        if (lane < 16) s_warpsum[lane] = ws;
        if (lane == 15) s_total = ws;
    }
    __syncthreads();

    const int warp_off = (warp > 0) ? s_warpsum[warp - 1] : 0;
    const int end      = warp_off + v;
    const int start    = end - d;
    const int total    = s_total;        // <= 512*7 = 3584 < 4096

    int16_t* f2r = g_frame2row + b * MAX_FRAMES;

    for (int p = start; p < end; ++p)
        f2r[p] = (int16_t)t;

    for (int p = total + t; p < MAX_FRAMES; p += SEQ_T)
        f2r[p] = (int16_t)(-1);

    if (t == 0)
        mel_lens_out[b] = (float)(total > 0 ? total : 1);
}

// ---------------------------------------------------------------------------
// Kernel B: hybrid gather. 16 consecutive frames per block.
//  - dedup consecutive identical source rows; warp-cooperative float4 loads
//    bring each distinct row into SMEM exactly once
//  - masked frames come from a zeroed SMEM slot (no read traffic)
//  - one cp.async.bulk (bulk_group) S->G per output row; no STG issue cost,
//    no mbarrier anywhere.
// ---------------------------------------------------------------------------
__global__ void __launch_bounds__(GB_THREADS)
lr_gather_hybrid(const float4* __restrict__ x,
                 float* __restrict__ out)
{
    // 16 data slots + 1 zero slot, each 2 KB  (34 KB static smem)
    __shared__ __align__(128) float4  s_data[(FPB + 1) * F4_ROW];
    __shared__ int16_t                s_r[FPB];

    const int bid  = blockIdx.x;
    const int b    = bid >> 8;                      // / (MAX_FRAMES/FPB)
    const int f0   = (bid & 255) * FPB;
    const int tid  = threadIdx.x;
    const int lane = tid & 31;
    const int warp = tid >> 5;                      // 0..3

    // zero the zero-slot (slot FPB): 128 threads x 16 B = 2048 B
    s_data[FPB * F4_ROW + tid] = make_float4(0.f, 0.f, 0.f, 0.f);

    if (tid < FPB)
        s_r[tid] = g_frame2row[b * MAX_FRAMES + f0 + tid];
    __syncthreads();

    // Dedup consecutive rows (computed redundantly by every thread; 16 iters).
    // slot[j] = SMEM slot feeding output frame j; rows[s] = source row of slot s
    int slot[FPB];
    int16_t rows[FPB];
    int nslots = 0, prev = -999;
    #pragma unroll
    for (int j = 0; j < FPB; ++j) {
        const int r = (int)s_r[j];
        if (r < 0)          slot[j] = FPB;                 // zero slot
        else if (r == prev) slot[j] = nslots - 1;          // reuse previous
        else { rows[nslots] = (int16_t)r; slot[j] = nslots++; prev = r; }
    }

    // Load phase: distinct rows round-robined across the 4 warps.
    // Each warp copies a 2 KB row: 32 lanes x 4 float4 (independent chains).
    const float4* __restrict__ xb = x + (size_t)b * SEQ_T * F4_ROW;
    for (int s = warp; s < nslots; s += 4) {
        const float4* __restrict__ src = xb + (int)rows[s] * F4_ROW;
        float4* __restrict__ dst = s_data + s * F4_ROW;
        #pragma unroll
        for (int i = 0; i < 4; ++i)
            dst[lane + 32 * i] = __ldg(&src[lane + 32 * i]);
    }
    __syncthreads();

    // Store phase: thread 0 issues one bulk S->G copy per output frame.
    if (tid == 0) {
        // order generic SMEM writes before async-proxy reads
        asm volatile("fence.proxy.async.shared::cta;" ::: "memory");

        const uint32_t sbase = s2u(s_data);
        float* obase = out + ((size_t)b * MAX_FRAMES + f0) * DIM;
        #pragma unroll
        for (int j = 0; j < FPB; ++j) {
            asm volatile(
                "cp.async.bulk.global.shared::cta.bulk_group [%0], [%1], %2;"
                :: "l"(obase + j * DIM), "r"(sbase + slot[j] * ROW_BYTES),
                   "n"(ROW_BYTES) : "memory");
        }
        asm volatile("cp.async.bulk.commit_group;" ::: "memory");
        asm volatile("cp.async.bulk.wait_group.read 0;" ::: "memory");
    }
    // __syncthreads not needed after: SMEM stays live until the CTA exits,
    // and wait_group.read guarantees the async proxy is done reading it.
    __syncthreads();
}

// ---------------------------------------------------------------------------
extern "C" void kernel_launch(void* const* d_in, const int* in_sizes, int n_in,
                              void* d_out, int out_size)
{
    const float* x         = (const float*)d_in[0];   // (32, 512, 512) f32
    const int*   durations = (const int*)d_in[1];     // (32, 512) i32
    float* out = (float*)d_out;

    float* mel_lens_out = out + (size_t)BATCH * MAX_FRAMES * DIM;

    lr_scan_map_kernel<<<BATCH, SEQ_T>>>(durations, mel_lens_out);
    lr_gather_hybrid<<<GB_GRID, GB_THREADS>>>((const float4*)x, out);
}

// round 5
// speedup vs baseline: 1.0339x; 1.0339x over previous
#include <cuda_runtime.h>
#include <cuda_bf16.h>
#include <stdint.h>

#define BATCH      32
#define SEQ_T      512
#define DIM        512
#define MAX_FRAMES 4096
#define BLOCK      256
#define FPB        32                              // frames per block
#define GRID       (BATCH * MAX_FRAMES / FPB)      // 4096

// ---------------------------------------------------------------------------
// Fused kernel: per-block scan of its batch's durations (redundant, L2-hot),
// binary-search rows for the block's 32 frames, then copy with 256-bit
// vector loads/stores. Each warp owns 4 frames = 8 independent 1KB chains.
// ---------------------------------------------------------------------------
__global__ void __launch_bounds__(BLOCK)
lr_fused(const float* __restrict__ x,
         const int* __restrict__ durations,
         float* __restrict__ out,
         float* __restrict__ mel_lens)
{
    __shared__ int s_ends[SEQ_T];
    __shared__ int s_wsum[8];

    const int bid  = blockIdx.x;
    const int b    = bid >> 7;                 // 128 blocks per batch
    const int f0   = (bid & 127) * FPB;
    const int tid  = threadIdx.x;
    const int lane = tid & 31;
    const int warp = tid >> 5;                 // 0..7

    // ---- inclusive scan of 512 durations (2 per thread, warp-shuffle) ----
    const int2 d2 = ((const int2*)(durations + b * SEQ_T))[tid];
    const int pairsum = d2.x + d2.y;
    int v = pairsum;
    #pragma unroll
    for (int off = 1; off < 32; off <<= 1) {
        int n = __shfl_up_sync(0xffffffffu, v, off);
        if (lane >= off) v += n;
    }
    if (lane == 31) s_wsum[warp] = v;
    __syncthreads();
    if (warp == 0 && lane < 8) {
        int ws = s_wsum[lane];
        #pragma unroll
        for (int off = 1; off < 8; off <<= 1) {
            int n = __shfl_up_sync(0x000000ffu, ws, off);
            if (lane >= off) ws += n;
        }
        s_wsum[lane] = ws;
    }
    __syncthreads();
    const int ebase = (warp > 0 ? s_wsum[warp - 1] : 0) + v - pairsum;
    s_ends[2 * tid]     = ebase + d2.x;
    s_ends[2 * tid + 1] = ebase + d2.x + d2.y;
    __syncthreads();

    const int total = s_ends[SEQ_T - 1];       // <= 3584 < 4096

    if ((bid & 127) == 0 && tid == 0)
        mel_lens[b] = (float)(total > 0 ? total : 1);

    // ---- rows for this warp's 4 frames: searchsorted(ends, pos, 'right') ----
    // lanes 0..3 (replicated mod 4) each search one frame, then broadcast.
    int idx = 0;
    {
        const int pos = f0 + warp * 4 + (lane & 3);
        #pragma unroll
        for (int s = 256; s > 0; s >>= 1)
            if (idx + s <= SEQ_T && s_ends[idx + s - 1] <= pos) idx += s;
    }
    int rows[4];
    rows[0] = min(__shfl_sync(0xffffffffu, idx, 0), SEQ_T - 1);
    rows[1] = min(__shfl_sync(0xffffffffu, idx, 1), SEQ_T - 1);
    rows[2] = min(__shfl_sync(0xffffffffu, idx, 2), SEQ_T - 1);
    rows[3] = min(__shfl_sync(0xffffffffu, idx, 3), SEQ_T - 1);
    bool msk[4];
    #pragma unroll
    for (int j = 0; j < 4; ++j)
        msk[j] = (f0 + warp * 4 + j) >= total;

    // ---- copy: 8 chains x 32B per lane, 256-bit vector ops ----
    const float* __restrict__ xb = x + (size_t)b * SEQ_T * DIM;
    float* __restrict__ ob =
        out + ((size_t)b * MAX_FRAMES + f0 + warp * 4) * DIM + lane * 8;

    float vbuf[8][8];

    #pragma unroll
    for (int k = 0; k < 8; ++k) {              // chain k = half-row k
        const int fr = k >> 1;
        if (msk[fr]) {
            #pragma unroll
            for (int i = 0; i < 8; ++i) vbuf[k][i] = 0.f;
        } else {
            const float* p = xb + rows[fr] * DIM + (k & 1) * 256 + lane * 8;
            asm volatile(
                "ld.global.nc.v8.f32 {%0,%1,%2,%3,%4,%5,%6,%7}, [%8];"
                : "=f"(vbuf[k][0]), "=f"(vbuf[k][1]),
                  "=f"(vbuf[k][2]), "=f"(vbuf[k][3]),
                  "=f"(vbuf[k][4]), "=f"(vbuf[k][5]),
                  "=f"(vbuf[k][6]), "=f"(vbuf[k][7])
                : "l"(p));
        }
    }

    #pragma unroll
    for (int k = 0; k < 8; ++k) {
        float* p = ob + k * 256;
        asm volatile(
            "st.global.cs.v8.f32 [%0], {%1,%2,%3,%4,%5,%6,%7,%8};"
            :: "l"(p),
               "f"(vbuf[k][0]), "f"(vbuf[k][1]),
               "f"(vbuf[k][2]), "f"(vbuf[k][3]),
               "f"(vbuf[k][4]), "f"(vbuf[k][5]),
               "f"(vbuf[k][6]), "f"(vbuf[k][7])
            : "memory");
    }
}

// ---------------------------------------------------------------------------
extern "C" void kernel_launch(void* const* d_in, const int* in_sizes, int n_in,
                              void* d_out, int out_size)
{
    const float* x         = (const float*)d_in[0];   // (32, 512, 512) f32
    const int*   durations = (const int*)d_in[1];     // (32, 512) i32
    float* out = (float*)d_out;
    float* mel_lens = out + (size_t)BATCH * MAX_FRAMES * DIM;

    lr_fused<<<GRID, BLOCK>>>(x, durations, out, mel_lens);
}

// round 6
// speedup vs baseline: 1.1061x; 1.0698x over previous
#include <cuda_runtime.h>
#include <cuda_bf16.h>
#include <stdint.h>

#define BATCH      32
#define SEQ_T      512
#define DIM        512
#define MAX_FRAMES 4096
#define F4_PER_ROW (DIM / 4)                           // 128
#define NB_F4      (MAX_FRAMES * F4_PER_ROW)           // 524288 f4 per batch
#define GK         8                                   // chains per thread
#define BLK        256
#define GB_PER_B   (NB_F4 / (BLK * GK))                // 256 gather blocks/batch
#define BSTRIDE    (NB_F4 / GK)                        // 65536

// frame -> source-row map; -1 means masked. 256 KB static scratch.
__device__ int16_t g_frame2row[BATCH * MAX_FRAMES];
// per-batch ready flags (sticky across graph replays; f2r is rewritten with
// identical values every launch, so consumers always read correct data)
__device__ volatile int g_ready[BATCH];

// ---------------------------------------------------------------------------
// Fused single launch: blocks 0..31 = producers (scan+scatter), rest = copy.
// ---------------------------------------------------------------------------
__global__ void __launch_bounds__(BLK)
lr_fused(const float4* __restrict__ x,
         const int* __restrict__ durations,
         float4* __restrict__ out,
         float* __restrict__ mel_lens)
{
    const int bid = blockIdx.x;
    const int tid = threadIdx.x;

    if (bid < BATCH) {
        // ================= producer: scan + scatter f2r =================
        const int b    = bid;
        const int lane = tid & 31;
        const int warp = tid >> 5;                 // 0..7

        __shared__ int s_wsum[8];
        __shared__ int s_total;

        // 2 durations per thread
        const int2 d2 = ((const int2*)(durations + b * SEQ_T))[tid];
        const int pairsum = d2.x + d2.y;

        int v = pairsum;
        #pragma unroll
        for (int off = 1; off < 32; off <<= 1) {
            int n = __shfl_up_sync(0xffffffffu, v, off);
            if (lane >= off) v += n;
        }
        if (lane == 31) s_wsum[warp] = v;
        __syncthreads();
        if (warp == 0 && lane < 8) {
            int ws = s_wsum[lane];
            #pragma unroll
            for (int off = 1; off < 8; off <<= 1) {
                int n = __shfl_up_sync(0x000000ffu, ws, off);
                if (lane >= off) ws += n;
            }
            s_wsum[lane] = ws;
            if (lane == 7) s_total = ws;
        }
        __syncthreads();

        const int ebase = (warp > 0 ? s_wsum[warp - 1] : 0) + v - pairsum;
        const int end0  = ebase + d2.x;            // end of row 2*tid
        const int end1  = end0 + d2.y;             // end of row 2*tid+1
        const int total = s_total;                 // <= 3584 < 4096

        int16_t* f2r = g_frame2row + b * MAX_FRAMES;

        for (int p = ebase; p < end0; ++p) f2r[p] = (int16_t)(2 * tid);
        for (int p = end0;  p < end1; ++p) f2r[p] = (int16_t)(2 * tid + 1);
        for (int p = total + tid; p < MAX_FRAMES; p += BLK)
            f2r[p] = (int16_t)(-1);

        if (tid == 0)
            mel_lens[b] = (float)(total > 0 ? total : 1);

        // release: make f2r visible, then set flag
        __syncthreads();
        __threadfence();
        if (tid == 0) g_ready[b] = 1;
    } else {
        // ================= consumer: R2-style K=8 float4 copy ===========
        const int gid   = bid - BATCH;
        const int b     = gid >> 8;                // / GB_PER_B
        const int local = gid & (GB_PER_B - 1);

        // acquire: wait for this batch's map
        if (tid == 0) {
            while (g_ready[b] == 0) { __nanosleep(64); }
        }
        __syncthreads();
        __threadfence();

        const int tg = local * BLK + tid;          // 0 .. 65535 within batch

        const int16_t* __restrict__ f2r = g_frame2row + b * MAX_FRAMES;
        const float4*  __restrict__ xb  = x + (size_t)b * SEQ_T * F4_PER_ROW;
        float4* __restrict__ ob         = out + (size_t)b * NB_F4;

        int idx[GK];
        int r  [GK];
        #pragma unroll
        for (int k = 0; k < GK; ++k) {
            idx[k] = tg + k * BSTRIDE;
            r[k]   = (int)f2r[idx[k] >> 7];
        }

        float4 vv[GK];
        #pragma unroll
        for (int k = 0; k < GK; ++k) {
            if (r[k] < 0) {
                vv[k] = make_float4(0.f, 0.f, 0.f, 0.f);
            } else {
                const int lane4 = idx[k] & (F4_PER_ROW - 1);
                vv[k] = __ldg(&xb[r[k] * F4_PER_ROW + lane4]);
            }
        }

        #pragma unroll
        for (int k = 0; k < GK; ++k)
            __stcs(&ob[idx[k]], vv[k]);
    }
}

// ---------------------------------------------------------------------------
extern "C" void kernel_launch(void* const* d_in, const int* in_sizes, int n_in,
                              void* d_out, int out_size)
{
    const float* x         = (const float*)d_in[0];   // (32, 512, 512) f32
    const int*   durations = (const int*)d_in[1];     // (32, 512) i32
    float* out = (float*)d_out;
    float* mel_lens = out + (size_t)BATCH * MAX_FRAMES * DIM;

    lr_fused<<<BATCH + BATCH * GB_PER_B, BLK>>>((const float4*)x, durations,
                                                (float4*)out, mel_lens);
}

// round 7
// speedup vs baseline: 1.1500x; 1.0397x over previous
#include <cuda_runtime.h>
#include <cuda_bf16.h>
#include <stdint.h>

#define BATCH      32
#define SEQ_T      512
#define DIM        512
#define MAX_FRAMES 4096
#define F4_ROW     (DIM / 4)                       // 128 float4 per row
#define FPB        16                              // frames per block
#define BLK        256
#define GK         8                               // float4 chains per thread
#define GRID       (BATCH * MAX_FRAMES / FPB)      // 8192
#define BLK_F4     (FPB * F4_ROW)                  // 2048 f4 per block
#define CH_STRIDE  (BLK_F4 / GK)                   // 256... no: BLK*GK=2048 => stride = BLK

// ---------------------------------------------------------------------------
// Single fused kernel, self-sufficient blocks:
//   scan own batch durations (L2-hot) -> rows for own 16 frames -> R2 copy.
// ---------------------------------------------------------------------------
__global__ void __launch_bounds__(BLK)
lr_fused2(const float4* __restrict__ x,
          const int* __restrict__ durations,
          float4* __restrict__ out,
          float* __restrict__ mel_lens)
{
    __shared__ int     s_ends[SEQ_T];
    __shared__ int     s_wsum[8];
    __shared__ int16_t s_row[FPB];     // -1 = masked

    const int bid  = blockIdx.x;
    const int b    = bid >> 8;                 // 256 blocks per batch
    const int f0   = (bid & 255) * FPB;
    const int tid  = threadIdx.x;
    const int lane = tid & 31;
    const int warp = tid >> 5;                 // 0..7

    // ---- inclusive scan of this batch's 512 durations (2/thread) ----
    const int2 d2 = ((const int2*)(durations + b * SEQ_T))[tid];
    const int pairsum = d2.x + d2.y;
    int v = pairsum;
    #pragma unroll
    for (int off = 1; off < 32; off <<= 1) {
        int n = __shfl_up_sync(0xffffffffu, v, off);
        if (lane >= off) v += n;
    }
    if (lane == 31) s_wsum[warp] = v;
    __syncthreads();
    if (warp == 0 && lane < 8) {
        int ws = s_wsum[lane];
        #pragma unroll
        for (int off = 1; off < 8; off <<= 1) {
            int n = __shfl_up_sync(0x000000ffu, ws, off);
            if (lane >= off) ws += n;
        }
        s_wsum[lane] = ws;
    }
    __syncthreads();
    const int ebase = (warp > 0 ? s_wsum[warp - 1] : 0) + v - pairsum;
    s_ends[2 * tid]     = ebase + d2.x;
    s_ends[2 * tid + 1] = ebase + d2.x + d2.y;
    __syncthreads();

    const int total = s_ends[SEQ_T - 1];       // <= 3584 < 4096

    // ---- rows for this block's 16 frames (16 threads search) ----
    if (tid < FPB) {
        const int pos = f0 + tid;
        if (pos >= total) {
            s_row[tid] = (int16_t)(-1);
        } else {
            int idx = 0;
            #pragma unroll
            for (int s = 256; s > 0; s >>= 1)
                if (idx + s <= SEQ_T && s_ends[idx + s - 1] <= pos) idx += s;
            s_row[tid] = (int16_t)min(idx, SEQ_T - 1);
        }
    }
    if ((bid & 255) == 0 && tid == 0)
        mel_lens[b] = (float)(total > 0 ? total : 1);
    __syncthreads();

    // ---- copy: R2-style 8 independent float4 chains per thread ----
    // block output region: 16 frames = 2048 f4; chain k handles f4
    // index tid + k*256 within the region (frames 2k / 2k+1 per chain pair).
    const float4* __restrict__ xb = x + (size_t)b * SEQ_T * F4_ROW;
    float4* __restrict__ ob = out + ((size_t)b * MAX_FRAMES + f0) * F4_ROW;

    int r[GK];
    #pragma unroll
    for (int k = 0; k < GK; ++k) {
        const int g  = tid + k * BLK;          // 0..2047 (BLK*GK = 2048)
        r[k] = (int)s_row[g >> 7];             // warp-uniform LDS broadcast
    }

    float4 vv[GK];
    #pragma unroll
    for (int k = 0; k < GK; ++k) {
        if (r[k] < 0) {
            vv[k] = make_float4(0.f, 0.f, 0.f, 0.f);
        } else {
            const int g     = tid + k * BLK;
            const int lane4 = g & (F4_ROW - 1);
            vv[k] = __ldg(&xb[r[k] * F4_ROW + lane4]);
        }
    }

    #pragma unroll
    for (int k = 0; k < GK; ++k)
        __stcs(&ob[tid + k * BLK], vv[k]);
}

// ---------------------------------------------------------------------------
extern "C" void kernel_launch(void* const* d_in, const int* in_sizes, int n_in,
                              void* d_out, int out_size)
{
    const float* x         = (const float*)d_in[0];   // (32, 512, 512) f32
    const int*   durations = (const int*)d_in[1];     // (32, 512) i32
    float* out = (float*)d_out;
    float* mel_lens = out + (size_t)BATCH * MAX_FRAMES * DIM;

    lr_fused2<<<GRID, BLK>>>((const float4*)x, durations,
                             (float4*)out, mel_lens);
}

// round 8
// speedup vs baseline: 1.1799x; 1.0260x over previous
#include <cuda_runtime.h>
#include <cuda_bf16.h>
#include <stdint.h>

#define BATCH      32
#define SEQ_T      512
#define DIM        512
#define MAX_FRAMES 4096
#define F4_ROW     (DIM / 4)                       // 128 float4 per row
#define FPB        32                              // frames per block
#define BLK        512
#define GK         8                               // float4 chains per thread
#define GRID       (BATCH * MAX_FRAMES / FPB)      // 4096
#define BLK_F4     (FPB * F4_ROW)                  // 4096 f4 per block (= BLK*GK)

// ---------------------------------------------------------------------------
// Single fused kernel, self-sufficient blocks:
//   scan own batch durations (L2-hot, 1/thread) -> rows for own 32 frames
//   -> 8 independent float4 chains per thread (ldg + stcs).
// ---------------------------------------------------------------------------
__global__ void __launch_bounds__(BLK)
lr_fused3(const float4* __restrict__ x,
          const int* __restrict__ durations,
          float4* __restrict__ out,
          float* __restrict__ mel_lens)
{
    __shared__ int     s_ends[SEQ_T];
    __shared__ int     s_wsum[16];
    __shared__ int16_t s_row[FPB];     // -1 = masked

    const int bid  = blockIdx.x;
    const int b    = bid >> 7;                 // 128 blocks per batch
    const int f0   = (bid & 127) * FPB;
    const int tid  = threadIdx.x;
    const int lane = tid & 31;
    const int warp = tid >> 5;                 // 0..15

    // ---- inclusive scan of this batch's 512 durations (1/thread) ----
    const int d = durations[b * SEQ_T + tid];
    int v = d;
    #pragma unroll
    for (int off = 1; off < 32; off <<= 1) {
        int n = __shfl_up_sync(0xffffffffu, v, off);
        if (lane >= off) v += n;
    }
    if (lane == 31) s_wsum[warp] = v;
    __syncthreads();
    if (warp == 0 && lane < 16) {
        int ws = s_wsum[lane];
        #pragma unroll
        for (int off = 1; off < 16; off <<= 1) {
            int n = __shfl_up_sync(0x0000ffffu, ws, off);
            if (lane >= off) ws += n;
        }
        s_wsum[lane] = ws;
    }
    __syncthreads();
    s_ends[tid] = (warp > 0 ? s_wsum[warp - 1] : 0) + v;
    __syncthreads();

    const int total = s_ends[SEQ_T - 1];       // <= 3584 < 4096

    // ---- rows for this block's 32 frames (32 threads search) ----
    if (tid < FPB) {
        const int pos = f0 + tid;
        if (pos >= total) {
            s_row[tid] = (int16_t)(-1);
        } else {
            int idx = 0;
            #pragma unroll
            for (int s = 256; s > 0; s >>= 1)
                if (idx + s <= SEQ_T && s_ends[idx + s - 1] <= pos) idx += s;
            s_row[tid] = (int16_t)min(idx, SEQ_T - 1);
        }
    }
    if ((bid & 127) == 0 && tid == 0)
        mel_lens[b] = (float)(total > 0 ? total : 1);
    __syncthreads();

    // ---- copy: 8 independent float4 chains per thread (proven R7 loop) ----
    const float4* __restrict__ xb = x + (size_t)b * SEQ_T * F4_ROW;
    float4* __restrict__ ob = out + ((size_t)b * MAX_FRAMES + f0) * F4_ROW;

    int r[GK];
    #pragma unroll
    for (int k = 0; k < GK; ++k) {
        const int g = tid + k * BLK;           // 0..4095
        r[k] = (int)s_row[g >> 7];             // warp-uniform LDS broadcast
    }

    float4 vv[GK];
    #pragma unroll
    for (int k = 0; k < GK; ++k) {
        if (r[k] < 0) {
            vv[k] = make_float4(0.f, 0.f, 0.f, 0.f);
        } else {
            const int g     = tid + k * BLK;
            const int lane4 = g & (F4_ROW - 1);
            vv[k] = __ldg(&xb[r[k] * F4_ROW + lane4]);
        }
    }

    #pragma unroll
    for (int k = 0; k < GK; ++k)
        __stcs(&ob[tid + k * BLK], vv[k]);
}

// ---------------------------------------------------------------------------
extern "C" void kernel_launch(void* const* d_in, const int* in_sizes, int n_in,
                              void* d_out, int out_size)
{
    const float* x         = (const float*)d_in[0];   // (32, 512, 512) f32
    const int*   durations = (const int*)d_in[1];     // (32, 512) i32
    float* out = (float*)d_out;
    float* mel_lens = out + (size_t)BATCH * MAX_FRAMES * DIM;

    lr_fused3<<<GRID, BLK>>>((const float4*)x, durations,
                             (float4*)out, mel_lens);
}